// round 2
// baseline (speedup 1.0000x reference)
#include <cuda_runtime.h>
#include <cstdint>
#include <cstddef>

#define DINLINE __device__ __forceinline__

namespace {
constexpr int Tlen = 512, U1 = 256, U2 = 128, OUTW = 24;
constexpr int CL = 8;        // CTAs per cluster (column split)
constexpr int Br = 16;       // batch rows per cluster
constexpr int NTHR = 128;

// SMEM layout in floats
constexpr int OFF_R1  = 0;                     // [256][96]
constexpr int OFF_K1  = OFF_R1 + 256 * 96;     // [64][96]
constexpr int OFF_K2  = OFF_K1 + 64 * 96;      // [256][48]
constexpr int OFF_R2  = OFF_K2 + 256 * 48;     // [128][48]
constexpr int OFF_H1  = OFF_R2 + 128 * 48;     // [16][256]
constexpr int OFF_H2  = OFF_H1 + Br * 256;     // [16][128]
constexpr int OFF_XS  = OFF_H2 + Br * 128;     // [2][16][64]
constexpr int OFF_B1X = OFF_XS + 2 * Br * 64;  // [96]
constexpr int OFF_B1H = OFF_B1X + 96;          // [96]
constexpr int OFF_B2X = OFF_B1H + 96;          // [48]
constexpr int OFF_B2H = OFF_B2X + 48;          // [48]
constexpr int SMEM_FLOATS = OFF_B2H + 48;      // 57632
constexpr size_t SMEM_BYTES = SMEM_FLOATS * sizeof(float);  // 230528 <= 232448
}  // namespace

DINLINE float sigf(float v) { return 1.0f / (1.0f + __expf(-v)); }
DINLINE float tanh_fast(float v) {
    float e = __expf(2.0f * fabsf(v));
    float t = 1.0f - 2.0f / (e + 1.0f);   // exp->inf => t->1 (overflow-safe)
    return copysignf(t, v);
}
DINLINE void cl_sync() {
    asm volatile("barrier.cluster.arrive.aligned;" ::: "memory");
    asm volatile("barrier.cluster.wait.aligned;" ::: "memory");
}
DINLINE uint32_t mapa_u32(uint32_t addr, uint32_t rank) {
    uint32_t p;
    asm("mapa.shared::cluster.u32 %0, %1, %2;" : "=r"(p) : "r"(addr), "r"(rank));
    return p;
}
DINLINE void st_remote_f32(uint32_t addr, float v) {
    asm volatile("st.shared::cluster.b32 [%0], %1;" :: "r"(addr), "r"(__float_as_uint(v)) : "memory");
}

__global__ void __launch_bounds__(NTHR, 1) __cluster_dims__(CL, 1, 1)
gru_stack_kernel(const float* __restrict__ x,  const float* __restrict__ k1,
                 const float* __restrict__ r1, const float* __restrict__ b1,
                 const float* __restrict__ k2, const float* __restrict__ r2,
                 const float* __restrict__ b2, const float* __restrict__ w3,
                 const float* __restrict__ b3, const float* __restrict__ w4,
                 const float* __restrict__ b4, const float* __restrict__ w5,
                 const float* __restrict__ b5, float* __restrict__ out)
{
    extern __shared__ float sm[];
    const int tid = threadIdx.x;
    const int c = blockIdx.x & (CL - 1);   // cluster rank (column slice)
    const int g = blockIdx.x >> 3;         // cluster id (batch tile)

    // ---- Stage weight slices into SMEM (once) ----
    // GRU1: unit slice c*32..c*32+31; local col j = gate*32 + lu
    for (int idx = tid; idx < 256 * 96; idx += NTHR) {
        int k = idx / 96, j = idx % 96;
        sm[OFF_R1 + idx] = r1[k * 768 + (j >> 5) * 256 + (c << 5) + (j & 31)];
    }
    for (int idx = tid; idx < 64 * 96; idx += NTHR) {
        int k = idx / 96, j = idx % 96;
        sm[OFF_K1 + idx] = k1[k * 768 + (j >> 5) * 256 + (c << 5) + (j & 31)];
    }
    // GRU2: unit slice c*16..c*16+15; local col j = gate*16 + lu
    for (int idx = tid; idx < 256 * 48; idx += NTHR) {
        int k = idx / 48, j = idx % 48;
        sm[OFF_K2 + idx] = k2[k * 384 + (j >> 4) * 128 + (c << 4) + (j & 15)];
    }
    for (int idx = tid; idx < 128 * 48; idx += NTHR) {
        int k = idx / 48, j = idx % 48;
        sm[OFF_R2 + idx] = r2[k * 384 + (j >> 4) * 128 + (c << 4) + (j & 15)];
    }
    if (tid < 96) {
        int gate = tid >> 5, lu = tid & 31;
        sm[OFF_B1X + tid] = b1[gate * 256 + (c << 5) + lu];
        sm[OFF_B1H + tid] = b1[768 + gate * 256 + (c << 5) + lu];
    }
    if (tid < 48) {
        int gate = tid >> 4, lu = tid & 15;
        sm[OFF_B2X + tid] = b2[gate * 128 + (c << 4) + lu];
        sm[OFF_B2H + tid] = b2[384 + gate * 128 + (c << 4) + lu];
    }
    for (int idx = tid; idx < Br * 256; idx += NTHR) sm[OFF_H1 + idx] = 0.0f;
    for (int idx = tid; idx < Br * 128; idx += NTHR) sm[OFF_H2 + idx] = 0.0f;
    // preload x(0) into buffer 0
    for (int i = tid; i < Br * 64; i += NTHR) {
        int r = i >> 6, f = i & 63;
        sm[OFF_XS + i] = x[((g * Br + r) * Tlen + 0) * 64 + f];
    }
    __syncthreads();
    cl_sync();

    const int row = tid >> 3;        // 0..15
    const int q   = tid & 7;         // 0..7
    const int lb1 = q << 2;          // 4 GRU1 units per thread (local)
    const int lb2 = q << 1;          // 2 GRU2 units per thread (local)

    uint32_t smem_base;
    asm("{ .reg .u64 t; cvta.to.shared.u64 t, %1; cvt.u32.u64 %0, t; }"
        : "=r"(smem_base) : "l"(sm));
    const uint32_t h1addr = smem_base + (uint32_t)(OFF_H1 + row * 256 + (c << 5) + lb1) * 4u;
    const uint32_t h2addr = smem_base + (uint32_t)(OFF_H2 + row * 128 + (c << 4) + lb2) * 4u;

    const float4* K1v = (const float4*)(sm + OFF_K1);
    const float4* R1v = (const float4*)(sm + OFF_R1);
    const float2* K2v = (const float2*)(sm + OFF_K2);
    const float2* R2v = (const float2*)(sm + OFF_R2);

    for (int t = 0; t < Tlen; t++) {
        const float* sx = sm + OFF_XS + (t & 1) * Br * 64;
        // prefetch x(t+1) into the other buffer (last read at step t-1, ordered by syncs)
        if (t + 1 < Tlen) {
            float* dx = sm + OFF_XS + ((t + 1) & 1) * Br * 64;
            #pragma unroll
            for (int i = 0; i < 8; i++) {
                int idx = tid + i * NTHR;
                int r = idx >> 6, f = idx & 63;
                dx[idx] = x[((g * Br + r) * Tlen + (t + 1)) * 64 + f];
            }
        }

        // ---------------- GRU1: row x 4 units ----------------
        float az[4], ar[4], ahx[4], ahh[4];
        #pragma unroll
        for (int i = 0; i < 4; i++) {
            az[i]  = sm[OFF_B1X + lb1 + i]      + sm[OFF_B1H + lb1 + i];
            ar[i]  = sm[OFF_B1X + 32 + lb1 + i] + sm[OFF_B1H + 32 + lb1 + i];
            ahx[i] = sm[OFF_B1X + 64 + lb1 + i];
            ahh[i] = sm[OFF_B1H + 64 + lb1 + i];
        }
        #pragma unroll 4
        for (int k = 0; k < 64; k++) {   // input projection (x @ k1)
            float v = sx[row * 64 + k];
            float4 wz = K1v[k * 24 + q];
            float4 wr = K1v[k * 24 + 8 + q];
            float4 wh = K1v[k * 24 + 16 + q];
            az[0]  += v * wz.x; az[1]  += v * wz.y; az[2]  += v * wz.z; az[3]  += v * wz.w;
            ar[0]  += v * wr.x; ar[1]  += v * wr.y; ar[2]  += v * wr.z; ar[3]  += v * wr.w;
            ahx[0] += v * wh.x; ahx[1] += v * wh.y; ahx[2] += v * wh.z; ahx[3] += v * wh.w;
        }
        #pragma unroll 4
        for (int k = 0; k < 256; k++) {  // recurrent projection (h1 @ r1)
            float v = sm[OFF_H1 + row * 256 + k];
            float4 wz = R1v[k * 24 + q];
            float4 wr = R1v[k * 24 + 8 + q];
            float4 wh = R1v[k * 24 + 16 + q];
            az[0]  += v * wz.x; az[1]  += v * wz.y; az[2]  += v * wz.z; az[3]  += v * wz.w;
            ar[0]  += v * wr.x; ar[1]  += v * wr.y; ar[2]  += v * wr.z; ar[3]  += v * wr.w;
            ahh[0] += v * wh.x; ahh[1] += v * wh.y; ahh[2] += v * wh.z; ahh[3] += v * wh.w;
        }
        float hn1[4];
        #pragma unroll
        for (int i = 0; i < 4; i++) {
            float z  = sigf(az[i]);
            float r  = sigf(ar[i]);
            float hh = tanh_fast(ahx[i] + r * ahh[i]);   // reset_after
            float hp = sm[OFF_H1 + row * 256 + (c << 5) + lb1 + i];
            hn1[i] = z * hp + (1.0f - z) * hh;
        }

        cl_sync();   // all ranks done reading h1(t-1)
        #pragma unroll
        for (int rr = 0; rr < CL; rr++) {   // replicate h1 slice to all ranks
            uint32_t pa = mapa_u32(h1addr, (uint32_t)rr);
            st_remote_f32(pa,      hn1[0]);
            st_remote_f32(pa + 4,  hn1[1]);
            st_remote_f32(pa + 8,  hn1[2]);
            st_remote_f32(pa + 12, hn1[3]);
        }
        cl_sync();   // h1(t) visible everywhere

        // ---------------- GRU2: row x 2 units ----------------
        float bz[2], brr[2], bhx[2], bhh[2];
        #pragma unroll
        for (int i = 0; i < 2; i++) {
            bz[i]  = sm[OFF_B2X + lb2 + i]      + sm[OFF_B2H + lb2 + i];
            brr[i] = sm[OFF_B2X + 16 + lb2 + i] + sm[OFF_B2H + 16 + lb2 + i];
            bhx[i] = sm[OFF_B2X + 32 + lb2 + i];
            bhh[i] = sm[OFF_B2H + 32 + lb2 + i];
        }
        #pragma unroll 4
        for (int k = 0; k < 256; k++) {  // input projection (h1(t) @ k2)
            float v = sm[OFF_H1 + row * 256 + k];
            float2 wz = K2v[k * 24 + q];
            float2 wr = K2v[k * 24 + 8 + q];
            float2 wh = K2v[k * 24 + 16 + q];
            bz[0]  += v * wz.x; bz[1]  += v * wz.y;
            brr[0] += v * wr.x; brr[1] += v * wr.y;
            bhx[0] += v * wh.x; bhx[1] += v * wh.y;
        }
        #pragma unroll 4
        for (int k = 0; k < 128; k++) {  // recurrent projection (h2 @ r2)
            float v = sm[OFF_H2 + row * 128 + k];
            float2 wz = R2v[k * 24 + q];
            float2 wr = R2v[k * 24 + 8 + q];
            float2 wh = R2v[k * 24 + 16 + q];
            bz[0]  += v * wz.x; bz[1]  += v * wz.y;
            brr[0] += v * wr.x; brr[1] += v * wr.y;
            bhh[0] += v * wh.x; bhh[1] += v * wh.y;
        }
        float hn2[2];
        #pragma unroll
        for (int i = 0; i < 2; i++) {
            float z  = sigf(bz[i]);
            float r  = sigf(brr[i]);
            float hh = tanh_fast(bhx[i] + r * bhh[i]);
            float hp = sm[OFF_H2 + row * 128 + (c << 4) + lb2 + i];
            hn2[i] = z * hp + (1.0f - z) * hh;
        }

        cl_sync();   // all ranks done reading h2(t-1)
        #pragma unroll
        for (int rr = 0; rr < CL; rr++) {
            uint32_t pa = mapa_u32(h2addr, (uint32_t)rr);
            st_remote_f32(pa,     hn2[0]);
            st_remote_f32(pa + 4, hn2[1]);
        }
        // h2(t) visibility for next step's GRU2 read is ordered by next step's syncs
    }
    cl_sync();   // final h2 replication complete

    // ---------------- Dense head (rank 0 of each cluster) ----------------
    if (c == 0) {
        float* sD3 = sm + OFF_XS;            // [16][64]
        float* sD4 = sm + OFF_XS + Br * 64;  // [16][32]
        for (int idx = tid; idx < Br * 64; idx += NTHR) {
            int r = idx >> 6, o = idx & 63;
            float a = b3[o];
            #pragma unroll 8
            for (int k = 0; k < 128; k++) a += sm[OFF_H2 + r * 128 + k] * w3[k * 64 + o];
            sD3[idx] = a;
        }
        __syncthreads();
        for (int idx = tid; idx < Br * 32; idx += NTHR) {
            int r = idx >> 5, o = idx & 31;
            float a = b4[o];
            #pragma unroll 8
            for (int k = 0; k < 64; k++) a += sD3[r * 64 + k] * w4[k * 32 + o];
            sD4[idx] = a;
        }
        __syncthreads();
        for (int idx = tid; idx < Br * OUTW; idx += NTHR) {
            int r = idx / OUTW, o = idx % OUTW;
            float a = b5[o];
            #pragma unroll 8
            for (int k = 0; k < 32; k++) a += sD4[r * 32 + k] * w5[k * OUTW + o];
            out[(g * Br + r) * OUTW + o] = a;
        }
    }
}

extern "C" void kernel_launch(void* const* d_in, const int* in_sizes, int n_in,
                              void* d_out, int out_size) {
    (void)in_sizes; (void)n_in; (void)out_size;
    const float* x  = (const float*)d_in[0];
    const float* k1 = (const float*)d_in[1];
    const float* r1 = (const float*)d_in[2];
    const float* b1 = (const float*)d_in[3];
    const float* k2 = (const float*)d_in[4];
    const float* r2 = (const float*)d_in[5];
    const float* b2 = (const float*)d_in[6];
    const float* w3 = (const float*)d_in[7];
    const float* b3 = (const float*)d_in[8];
    const float* w4 = (const float*)d_in[9];
    const float* b4 = (const float*)d_in[10];
    const float* w5 = (const float*)d_in[11];
    const float* b5 = (const float*)d_in[12];
    float* out = (float*)d_out;

    cudaFuncSetAttribute(gru_stack_kernel,
                         cudaFuncAttributeMaxDynamicSharedMemorySize,
                         (int)SMEM_BYTES);
    gru_stack_kernel<<<128, NTHR, SMEM_BYTES>>>(
        x, k1, r1, b1, k2, r2, b2, w3, b3, w4, b4, w5, b5, out);
}

// round 3
// speedup vs baseline: 1.7865x; 1.7865x over previous
#include <cuda_runtime.h>
#include <cstdint>
#include <cstddef>

typedef unsigned long long ull;
#define DINLINE __device__ __forceinline__

namespace {
constexpr int Tlen = 512, OUTW = 24;
constexpr int CL = 8;        // CTAs per cluster (column split)
constexpr int Br = 16;       // batch rows per cluster
constexpr int NTHR = 128;

// padded strides (stride % 32 == 2 or 4 -> conflict-free warp row access)
constexpr int H1S = 258;     // H1 row stride (floats)
constexpr int H2S = 130;
constexpr int XSS = 68;      // x tile row stride (16B-aligned rows for cp.async)

constexpr int OFF_R1 = 0;                    // [256][96]
constexpr int OFF_K1 = OFF_R1 + 256 * 96;    // [64][96]
constexpr int OFF_K2 = OFF_K1 + 64 * 96;     // [256][48]
constexpr int OFF_R2 = OFF_K2 + 256 * 48;    // [128][48]
constexpr int OFF_H1 = OFF_R2 + 128 * 48;    // [16][258]
constexpr int OFF_H2 = OFF_H1 + Br * H1S;    // [16][130]
constexpr int OFF_XS = OFF_H2 + Br * H2S;    // [16][68]
constexpr int OFF_SC = OFF_XS + Br * XSS;    // scratch: 3*16*34 floats
constexpr int SMEM_FLOATS = OFF_SC + 3 * 16 * 34;   // 58080
constexpr size_t SMEM_BYTES = SMEM_FLOATS * sizeof(float);  // 232320
}  // namespace

DINLINE float sigf(float v) { return 1.0f / (1.0f + __expf(-v)); }
DINLINE float tanh_fast(float v) {
    float e = __expf(2.0f * fabsf(v));
    float t = 1.0f - 2.0f / (e + 1.0f);
    return copysignf(t, v);
}
DINLINE void cl_arrive() { asm volatile("barrier.cluster.arrive.aligned;" ::: "memory"); }
DINLINE void cl_wait()   { asm volatile("barrier.cluster.wait.aligned;"   ::: "memory"); }
DINLINE uint32_t mapa_u32(uint32_t addr, uint32_t rank) {
    uint32_t p;
    asm("mapa.shared::cluster.u32 %0, %1, %2;" : "=r"(p) : "r"(addr), "r"(rank));
    return p;
}
DINLINE void st_rem64(uint32_t addr, ull v) {
    asm volatile("st.shared::cluster.b64 [%0], %1;" :: "r"(addr), "l"(v) : "memory");
}
DINLINE ull pk2(float a, float b) {
    ull r; asm("mov.b64 %0, {%1, %2};" : "=l"(r) : "f"(a), "f"(b)); return r;
}
DINLINE float2 upk(ull v) {
    float2 r; asm("mov.b64 {%0, %1}, %2;" : "=f"(r.x), "=f"(r.y) : "l"(v)); return r;
}
DINLINE void f2(ull& d, ull a, ull b) {          // d += a*b (packed fp32x2)
    asm("fma.rn.f32x2 %0, %1, %2, %0;" : "+l"(d) : "l"(a), "l"(b));
}
DINLINE void a2(ull& d, ull b) {                 // d += b (packed fp32x2)
    asm("add.rn.f32x2 %0, %0, %1;" : "+l"(d) : "l"(b));
}
DINLINE void cp_async16(uint32_t sa, const void* ga) {
    asm volatile("cp.async.ca.shared.global [%0], [%1], 16;" :: "r"(sa), "l"(ga) : "memory");
}

__global__ void __launch_bounds__(NTHR, 1) __cluster_dims__(CL, 1, 1)
gru_stack_kernel(const float* __restrict__ x,  const float* __restrict__ k1,
                 const float* __restrict__ r1, const float* __restrict__ b1,
                 const float* __restrict__ k2, const float* __restrict__ r2,
                 const float* __restrict__ b2, const float* __restrict__ w3,
                 const float* __restrict__ b3, const float* __restrict__ w4,
                 const float* __restrict__ b4, const float* __restrict__ w5,
                 const float* __restrict__ b5, float* __restrict__ out)
{
    extern __shared__ float sm[];
    const int tid = threadIdx.x;
    const int c = blockIdx.x & (CL - 1);
    const int g = blockIdx.x >> 3;

    // ---- Stage weight slices (layouts: [k][cols], col j = gate*U + local_unit) ----
    for (int idx = tid; idx < 256 * 96; idx += NTHR) {
        int k = idx / 96, j = idx % 96;
        sm[OFF_R1 + idx] = r1[k * 768 + (j >> 5) * 256 + (c << 5) + (j & 31)];
    }
    for (int idx = tid; idx < 64 * 96; idx += NTHR) {
        int k = idx / 96, j = idx % 96;
        sm[OFF_K1 + idx] = k1[k * 768 + (j >> 5) * 256 + (c << 5) + (j & 31)];
    }
    for (int idx = tid; idx < 256 * 48; idx += NTHR) {
        int k = idx / 48, j = idx % 48;
        sm[OFF_K2 + idx] = k2[k * 384 + (j >> 4) * 128 + (c << 4) + (j & 15)];
    }
    for (int idx = tid; idx < 128 * 48; idx += NTHR) {
        int k = idx / 48, j = idx % 48;
        sm[OFF_R2 + idx] = r2[k * 384 + (j >> 4) * 128 + (c << 4) + (j & 15)];
    }
    for (int idx = tid; idx < Br * H1S; idx += NTHR) sm[OFF_H1 + idx] = 0.0f;
    for (int idx = tid; idx < Br * H2S; idx += NTHR) sm[OFF_H2 + idx] = 0.0f;
    for (int i = tid; i < Br * 64; i += NTHR) {      // x(0)
        int r = i >> 6, f = i & 63;
        sm[OFF_XS + r * XSS + f] = x[(size_t)((g * Br + r) * Tlen + 0) * 64 + f];
    }

    // ---- thread mappings ----
    const int kcA = tid >> 6, rgA = (tid >> 3) & 7, ctA = tid & 7;   // GRU1
    const int kcB = tid >> 5, rgB = (tid >> 2) & 7, ctB = tid & 3;   // GRU2
    const int rA0 = rgA * 2, rB0 = rgB * 2;

    // ---- biases in registers (packed pairs), gate-owner threads only ----
    ull bzA[2], brA[2], bxA[2], bhA[2];
    if (kcA == 0) {
        #pragma unroll
        for (int p = 0; p < 2; p++) {
            int u0 = (c << 5) + ctA * 4 + p * 2, u1 = u0 + 1;
            bzA[p] = pk2(b1[u0] + b1[768 + u0],             b1[u1] + b1[768 + u1]);
            brA[p] = pk2(b1[256 + u0] + b1[1024 + u0],      b1[256 + u1] + b1[1024 + u1]);
            bxA[p] = pk2(b1[512 + u0],                      b1[512 + u1]);
            bhA[p] = pk2(b1[1280 + u0],                     b1[1280 + u1]);
        }
    }
    ull bzB[2], brB[2], bxB[2], bhB[2];
    if (kcB == 0) {
        #pragma unroll
        for (int p = 0; p < 2; p++) {
            int u0 = (c << 4) + ctB * 4 + p * 2, u1 = u0 + 1;
            bzB[p] = pk2(b2[u0] + b2[384 + u0],             b2[u1] + b2[384 + u1]);
            brB[p] = pk2(b2[128 + u0] + b2[512 + u0],       b2[128 + u1] + b2[512 + u1]);
            bxB[p] = pk2(b2[256 + u0],                      b2[256 + u1]);
            bhB[p] = pk2(b2[640 + u0],                      b2[640 + u1]);
        }
    }

    uint32_t smem_base;
    asm("{ .reg .u64 t; cvta.to.shared.u64 t, %1; cvt.u32.u64 %0, t; }"
        : "=r"(smem_base) : "l"(sm));
    const uint32_t h1la = smem_base + (uint32_t)(OFF_H1 + rA0 * H1S + (c << 5) + ctA * 4) * 4u;
    const uint32_t h2la = smem_base + (uint32_t)(OFF_H2 + rB0 * H2S + (c << 4) + ctB * 4) * 4u;

    const ulonglong2* K1p = (const ulonglong2*)(sm + OFF_K1);
    const ulonglong2* R1p = (const ulonglong2*)(sm + OFF_R1);
    const ulonglong2* K2p = (const ulonglong2*)(sm + OFF_K2);
    const ulonglong2* R2p = (const ulonglong2*)(sm + OFF_R2);
    ull* scU = (ull*)(sm + OFF_SC);

    __syncthreads();
    cl_arrive(); cl_wait();

    for (int t = 0; t < Tlen; t++) {
        // ================= GRU1 =================
        ull az[2][2], ar[2][2], ax[2][2], ah[2][2];
        #pragma unroll
        for (int rr = 0; rr < 2; rr++)
            #pragma unroll
            for (int p = 0; p < 2; p++) {
                az[rr][p] = (kcA == 0) ? bzA[p] : 0ull;
                ar[rr][p] = (kcA == 0) ? brA[p] : 0ull;
                ax[rr][p] = (kcA == 0) ? bxA[p] : 0ull;
                ah[rr][p] = (kcA == 0) ? bhA[p] : 0ull;
            }
        if (kcA == 0) {  // input projection x @ k1 (k = 0..63)
            const float* x0 = sm + OFF_XS + rA0 * XSS;
            const float* x1 = x0 + XSS;
            #pragma unroll 4
            for (int k = 0; k < 64; k++) {
                ull v0 = pk2(x0[k], x0[k]), v1 = pk2(x1[k], x1[k]);
                ulonglong2 wz = K1p[k * 24 + ctA];
                ulonglong2 wr = K1p[k * 24 + 8 + ctA];
                ulonglong2 wh = K1p[k * 24 + 16 + ctA];
                f2(az[0][0], v0, wz.x); f2(az[0][1], v0, wz.y);
                f2(az[1][0], v1, wz.x); f2(az[1][1], v1, wz.y);
                f2(ar[0][0], v0, wr.x); f2(ar[0][1], v0, wr.y);
                f2(ar[1][0], v1, wr.x); f2(ar[1][1], v1, wr.y);
                f2(ax[0][0], v0, wh.x); f2(ax[0][1], v0, wh.y);
                f2(ax[1][0], v1, wh.x); f2(ax[1][1], v1, wh.y);
            }
        }
        {   // recurrent projection h1 @ r1 (kc0: k 0..95, kc1: k 96..255)
            const int kb = kcA ? 96 : 0, ke = kcA ? 256 : 96;
            const float* h0 = sm + OFF_H1 + rA0 * H1S;
            const float* h1r = h0 + H1S;
            #pragma unroll 4
            for (int k = kb; k < ke; k++) {
                ull v0 = pk2(h0[k], h0[k]), v1 = pk2(h1r[k], h1r[k]);
                ulonglong2 wz = R1p[k * 24 + ctA];
                ulonglong2 wr = R1p[k * 24 + 8 + ctA];
                ulonglong2 wh = R1p[k * 24 + 16 + ctA];
                f2(az[0][0], v0, wz.x); f2(az[0][1], v0, wz.y);
                f2(az[1][0], v1, wz.x); f2(az[1][1], v1, wz.y);
                f2(ar[0][0], v0, wr.x); f2(ar[0][1], v0, wr.y);
                f2(ar[1][0], v1, wr.x); f2(ar[1][1], v1, wr.y);
                f2(ah[0][0], v0, wh.x); f2(ah[0][1], v0, wh.y);
                f2(ah[1][0], v1, wh.x); f2(ah[1][1], v1, wh.y);
            }
        }
        cl_arrive();                         // #1: done reading h1(t-1)
        if (kcA == 1) {                      // store partials (z,r,hrec)
            #pragma unroll
            for (int rr = 0; rr < 2; rr++) {
                int r = rA0 + rr;
                #pragma unroll
                for (int p = 0; p < 2; p++) {
                    scU[r * 50 +      ctA * 2 + p] = az[rr][p];
                    scU[r * 50 + 16 + ctA * 2 + p] = ar[rr][p];
                    scU[r * 50 + 32 + ctA * 2 + p] = ah[rr][p];
                }
            }
        }
        __syncthreads();
        float hn1[2][4];
        if (kcA == 0) {
            #pragma unroll
            for (int rr = 0; rr < 2; rr++) {
                int r = rA0 + rr;
                #pragma unroll
                for (int p = 0; p < 2; p++) {
                    a2(az[rr][p], scU[r * 50 +      ctA * 2 + p]);
                    a2(ar[rr][p], scU[r * 50 + 16 + ctA * 2 + p]);
                    a2(ah[rr][p], scU[r * 50 + 32 + ctA * 2 + p]);
                    float2 vz = upk(az[rr][p]), vr = upk(ar[rr][p]);
                    float2 vx = upk(ax[rr][p]), vh = upk(ah[rr][p]);
                    int col = (c << 5) + ctA * 4 + p * 2;
                    float hp0 = sm[OFF_H1 + r * H1S + col];
                    float hp1 = sm[OFF_H1 + r * H1S + col + 1];
                    float z0 = sigf(vz.x), r0g = sigf(vr.x);
                    float hh0 = tanh_fast(vx.x + r0g * vh.x);
                    float z1 = sigf(vz.y), r1g = sigf(vr.y);
                    float hh1 = tanh_fast(vx.y + r1g * vh.y);
                    hn1[rr][p * 2]     = z0 * hp0 + (1.0f - z0) * hh0;
                    hn1[rr][p * 2 + 1] = z1 * hp1 + (1.0f - z1) * hh1;
                }
            }
        } else if (t + 1 < Tlen) {           // prefetch x(t+1) via cp.async
            int base = (tid - 64) * 4;
            #pragma unroll
            for (int j = 0; j < 4; j++) {
                int i = base + j, r = i >> 4, f4 = i & 15;
                uint32_t sa = smem_base + (uint32_t)(OFF_XS + r * XSS + f4 * 4) * 4u;
                const float* ga = x + (size_t)((g * Br + r) * Tlen + (t + 1)) * 64 + f4 * 4;
                cp_async16(sa, ga);
            }
            asm volatile("cp.async.commit_group;" ::: "memory");
        }
        cl_wait();                           // #1 complete
        if (kcA == 0) {                      // replicate h1(t) to all ranks
            ull q00 = pk2(hn1[0][0], hn1[0][1]), q01 = pk2(hn1[0][2], hn1[0][3]);
            ull q10 = pk2(hn1[1][0], hn1[1][1]), q11 = pk2(hn1[1][2], hn1[1][3]);
            #pragma unroll
            for (int rk = 0; rk < CL; rk++) {
                uint32_t p0 = mapa_u32(h1la, (uint32_t)rk);
                st_rem64(p0, q00); st_rem64(p0 + 8, q01);
                uint32_t p1 = mapa_u32(h1la + H1S * 4, (uint32_t)rk);
                st_rem64(p1, q10); st_rem64(p1 + 8, q11);
            }
        }
        cl_arrive(); cl_wait();              // #2: h1(t) visible everywhere

        // ================= GRU2 =================
        ull bz[2][2], br_[2][2], bx[2][2], bh[2][2];
        #pragma unroll
        for (int rr = 0; rr < 2; rr++)
            #pragma unroll
            for (int p = 0; p < 2; p++) {
                bz[rr][p] = (kcB == 0) ? bzB[p] : 0ull;
                br_[rr][p] = (kcB == 0) ? brB[p] : 0ull;
                bx[rr][p] = (kcB == 0) ? bxB[p] : 0ull;
                bh[rr][p] = (kcB == 0) ? bhB[p] : 0ull;
            }
        {   // input projection h1(t) @ k2 (64 k per chunk)
            const float* h0 = sm + OFF_H1 + rB0 * H1S;
            const float* h1r = h0 + H1S;
            const int kb = kcB * 64;
            #pragma unroll 4
            for (int kk = 0; kk < 64; kk++) {
                int k = kb + kk;
                ull v0 = pk2(h0[k], h0[k]), v1 = pk2(h1r[k], h1r[k]);
                ulonglong2 wz = K2p[k * 12 + ctB];
                ulonglong2 wr = K2p[k * 12 + 4 + ctB];
                ulonglong2 wh = K2p[k * 12 + 8 + ctB];
                f2(bz[0][0], v0, wz.x); f2(bz[0][1], v0, wz.y);
                f2(bz[1][0], v1, wz.x); f2(bz[1][1], v1, wz.y);
                f2(br_[0][0], v0, wr.x); f2(br_[0][1], v0, wr.y);
                f2(br_[1][0], v1, wr.x); f2(br_[1][1], v1, wr.y);
                f2(bx[0][0], v0, wh.x); f2(bx[0][1], v0, wh.y);
                f2(bx[1][0], v1, wh.x); f2(bx[1][1], v1, wh.y);
            }
        }
        {   // recurrent projection h2 @ r2 (32 k per chunk)
            const float* h0 = sm + OFF_H2 + rB0 * H2S;
            const float* h1r = h0 + H2S;
            const int kb = kcB * 32;
            #pragma unroll 4
            for (int kk = 0; kk < 32; kk++) {
                int k = kb + kk;
                ull v0 = pk2(h0[k], h0[k]), v1 = pk2(h1r[k], h1r[k]);
                ulonglong2 wz = R2p[k * 12 + ctB];
                ulonglong2 wr = R2p[k * 12 + 4 + ctB];
                ulonglong2 wh = R2p[k * 12 + 8 + ctB];
                f2(bz[0][0], v0, wz.x); f2(bz[0][1], v0, wz.y);
                f2(bz[1][0], v1, wz.x); f2(bz[1][1], v1, wz.y);
                f2(br_[0][0], v0, wr.x); f2(br_[0][1], v0, wr.y);
                f2(br_[1][0], v1, wr.x); f2(br_[1][1], v1, wr.y);
                f2(bh[0][0], v0, wh.x); f2(bh[0][1], v0, wh.y);
                f2(bh[1][0], v1, wh.x); f2(bh[1][1], v1, wh.y);
            }
        }
        cl_arrive();                         // #3: done reading h2(t-1)
        if (kcB > 0) {                       // round 1: z, r partials
            if (tid >= 64) asm volatile("cp.async.wait_group 0;" ::: "memory");
            int m = kcB - 1;
            #pragma unroll
            for (int rr = 0; rr < 2; rr++) {
                int r = rB0 + rr;
                #pragma unroll
                for (int p = 0; p < 2; p++) {
                    scU[m * 272 + r * 17 +     ctB * 2 + p] = bz[rr][p];
                    scU[m * 272 + r * 17 + 8 + ctB * 2 + p] = br_[rr][p];
                }
            }
        }
        __syncthreads();
        if (kcB == 0) {
            #pragma unroll
            for (int m = 0; m < 3; m++)
                #pragma unroll
                for (int rr = 0; rr < 2; rr++) {
                    int r = rB0 + rr;
                    #pragma unroll
                    for (int p = 0; p < 2; p++) {
                        a2(bz[rr][p],  scU[m * 272 + r * 17 +     ctB * 2 + p]);
                        a2(br_[rr][p], scU[m * 272 + r * 17 + 8 + ctB * 2 + p]);
                    }
                }
        }
        __syncthreads();
        if (kcB > 0) {                       // round 2: hx, hh partials
            int m = kcB - 1;
            #pragma unroll
            for (int rr = 0; rr < 2; rr++) {
                int r = rB0 + rr;
                #pragma unroll
                for (int p = 0; p < 2; p++) {
                    scU[m * 272 + r * 17 +     ctB * 2 + p] = bx[rr][p];
                    scU[m * 272 + r * 17 + 8 + ctB * 2 + p] = bh[rr][p];
                }
            }
        }
        __syncthreads();
        float hn2[2][4];
        if (kcB == 0) {
            #pragma unroll
            for (int rr = 0; rr < 2; rr++) {
                int r = rB0 + rr;
                #pragma unroll
                for (int p = 0; p < 2; p++) {
                    #pragma unroll
                    for (int m = 0; m < 3; m++) {
                        a2(bx[rr][p], scU[m * 272 + r * 17 +     ctB * 2 + p]);
                        a2(bh[rr][p], scU[m * 272 + r * 17 + 8 + ctB * 2 + p]);
                    }
                    float2 vz = upk(bz[rr][p]), vr = upk(br_[rr][p]);
                    float2 vx = upk(bx[rr][p]), vh = upk(bh[rr][p]);
                    int col = (c << 4) + ctB * 4 + p * 2;
                    float hp0 = sm[OFF_H2 + r * H2S + col];
                    float hp1 = sm[OFF_H2 + r * H2S + col + 1];
                    float z0 = sigf(vz.x), r0g = sigf(vr.x);
                    float hh0 = tanh_fast(vx.x + r0g * vh.x);
                    float z1 = sigf(vz.y), r1g = sigf(vr.y);
                    float hh1 = tanh_fast(vx.y + r1g * vh.y);
                    hn2[rr][p * 2]     = z0 * hp0 + (1.0f - z0) * hh0;
                    hn2[rr][p * 2 + 1] = z1 * hp1 + (1.0f - z1) * hh1;
                }
            }
        }
        cl_wait();                           // #3 complete
        if (kcB == 0) {                      // replicate h2(t)
            ull q00 = pk2(hn2[0][0], hn2[0][1]), q01 = pk2(hn2[0][2], hn2[0][3]);
            ull q10 = pk2(hn2[1][0], hn2[1][1]), q11 = pk2(hn2[1][2], hn2[1][3]);
            #pragma unroll
            for (int rk = 0; rk < CL; rk++) {
                uint32_t p0 = mapa_u32(h2la, (uint32_t)rk);
                st_rem64(p0, q00); st_rem64(p0 + 8, q01);
                uint32_t p1 = mapa_u32(h2la + H2S * 4, (uint32_t)rk);
                st_rem64(p1, q10); st_rem64(p1 + 8, q11);
            }
        }
    }
    cl_arrive(); cl_wait();                  // final h2 replication visible

    // ================= Dense head (rank 0) =================
    if (c == 0) {
        float* sD3 = sm + OFF_SC;            // [16][64]
        float* sD4 = sm + OFF_SC + Br * 64;  // [16][32]
        __syncthreads();
        for (int idx = tid; idx < Br * 64; idx += NTHR) {
            int r = idx >> 6, o = idx & 63;
            float a = b3[o];
            #pragma unroll 8
            for (int k = 0; k < 128; k++) a += sm[OFF_H2 + r * H2S + k] * w3[k * 64 + o];
            sD3[idx] = a;
        }
        __syncthreads();
        for (int idx = tid; idx < Br * 32; idx += NTHR) {
            int r = idx >> 5, o = idx & 31;
            float a = b4[o];
            #pragma unroll 8
            for (int k = 0; k < 64; k++) a += sD3[r * 64 + k] * w4[k * 32 + o];
            sD4[idx] = a;
        }
        __syncthreads();
        for (int idx = tid; idx < Br * OUTW; idx += NTHR) {
            int r = idx / OUTW, o = idx % OUTW;
            float a = b5[o];
            #pragma unroll 8
            for (int k = 0; k < 32; k++) a += sD4[r * 32 + k] * w5[k * OUTW + o];
            out[(g * Br + r) * OUTW + o] = a;
        }
    }
}

extern "C" void kernel_launch(void* const* d_in, const int* in_sizes, int n_in,
                              void* d_out, int out_size) {
    (void)in_sizes; (void)n_in; (void)out_size;
    const float* x  = (const float*)d_in[0];
    const float* k1 = (const float*)d_in[1];
    const float* r1 = (const float*)d_in[2];
    const float* b1 = (const float*)d_in[3];
    const float* k2 = (const float*)d_in[4];
    const float* r2 = (const float*)d_in[5];
    const float* b2 = (const float*)d_in[6];
    const float* w3 = (const float*)d_in[7];
    const float* b3 = (const float*)d_in[8];
    const float* w4 = (const float*)d_in[9];
    const float* b4 = (const float*)d_in[10];
    const float* w5 = (const float*)d_in[11];
    const float* b5 = (const float*)d_in[12];
    float* out = (float*)d_out;

    cudaFuncSetAttribute(gru_stack_kernel,
                         cudaFuncAttributeMaxDynamicSharedMemorySize,
                         (int)SMEM_BYTES);
    gru_stack_kernel<<<128, NTHR, SMEM_BYTES>>>(
        x, k1, r1, b1, k2, r2, b2, w3, b3, w4, b4, w5, b5, out);
}